// round 7
// baseline (speedup 1.0000x reference)
#include <cuda_runtime.h>
#include <cuda_bf16.h>
#include <cstdint>
#include <math.h>

// ---------------------------------------------------------------------------
// stack_latent_attention (B=16, NV=NH=D=1024)
// GEMMs via mma.sync.m16n8k16 bf16, split-bf16 3-term (hh + hl + lh).
// R7: R5-proven 128x128 tile / 64x32 warp tile, BK=32, 2-stage cp.async,
//     2 CTAs/SM (80KB smem/CTA, launch_bounds(256,2)).
// ---------------------------------------------------------------------------

#define BB    16
#define NVV   1024
#define DD    1024
#define MROWS (BB * NVV)
#define NEGV  (-1e30f)

// ============================ PTX helpers ===================================
__device__ __forceinline__ uint32_t smem_u32(const void* p) {
    uint32_t a;
    asm("{ .reg .u64 t; cvta.to.shared.u64 t, %1; cvt.u32.u64 %0, t; }"
        : "=r"(a) : "l"(p));
    return a;
}

#define CP16(s, g) \
    asm volatile("cp.async.cg.shared.global [%0], [%1], 16;" \
                 :: "r"(s), "l"(g) : "memory")

#define LDSM4(r, addr) \
    asm volatile("ldmatrix.sync.aligned.m8n8.x4.shared.b16 {%0,%1,%2,%3}, [%4];" \
                 : "=r"((r)[0]), "=r"((r)[1]), "=r"((r)[2]), "=r"((r)[3]) \
                 : "r"(addr))

#define MMA(c, a, b0, b1) \
    asm volatile("mma.sync.aligned.m16n8k16.row.col.f32.bf16.bf16.f32 " \
                 "{%0,%1,%2,%3}, {%4,%5,%6,%7}, {%8,%9}, {%0,%1,%2,%3};" \
                 : "+f"((c)[0]), "+f"((c)[1]), "+f"((c)[2]), "+f"((c)[3]) \
                 : "r"((a)[0]), "r"((a)[1]), "r"((a)[2]), "r"((a)[3]), \
                   "r"(b0), "r"(b1))

// ============================ scratch =======================================
__device__ __align__(256) __nv_bfloat16 g_vhi[MROWS * DD], g_vlo[MROWS * DD];
__device__ __align__(256) __nv_bfloat16 g_hhi[MROWS * DD], g_hlo[MROWS * DD];
__device__ __align__(256) __nv_bfloat16 g_zhi[MROWS * 2 * DD], g_zlo[MROWS * 2 * DD];
__device__ __align__(256) __nv_bfloat16 g_Wvh[DD * DD], g_Wvl[DD * DD];
__device__ __align__(256) __nv_bfloat16 g_qvh[DD * DD], g_qvl[DD * DD];
__device__ __align__(256) __nv_bfloat16 g_Whh[DD * DD], g_Whl[DD * DD];
__device__ __align__(256) __nv_bfloat16 g_khh[DD * DD], g_khl[DD * DD];
__device__ __align__(256) __nv_bfloat16 g_Wzh[DD * 2 * DD], g_Wzl[DD * 2 * DD];
__device__ __align__(256) __nv_bfloat16 g_Qh[MROWS * DD],  g_Ql[MROWS * DD];
__device__ __align__(256) __nv_bfloat16 g_Kh[MROWS * DD],  g_Kl[MROWS * DD];
__device__ __align__(256) __nv_bfloat16 g_Ph[MROWS * DD],  g_Pl[MROWS * DD];
__device__ __align__(256) __nv_bfloat16 g_HTh[MROWS * DD], g_HTl[MROWS * DD];
__device__ __align__(256) float g_Vp[MROWS * DD];
__device__ __align__(256) float g_Hh[MROWS * DD];
__device__ __align__(256) float g_Zp[MROWS * DD];
__device__ __align__(256) float g_att[(long long)BB * NVV * NVV];
__device__ __align__(256) float g_Hv[MROWS * DD];
__device__ float g_u[MROWS];
__device__ float g_p[MROWS];
__device__ float g_g[BB * DD];

// ======================== conversion kernels ================================
__global__ __launch_bounds__(256)
void conv_split(const float* __restrict__ x, __nv_bfloat16* __restrict__ hi,
                __nv_bfloat16* __restrict__ lo, long long n4)
{
    long long i = (long long)blockIdx.x * 256 + threadIdx.x;
    if (i >= n4) return;
    float4 v = ((const float4*)x)[i];
    __nv_bfloat16 hh[4], ll[4];
    float f[4] = {v.x, v.y, v.z, v.w};
#pragma unroll
    for (int k = 0; k < 4; k++) {
        hh[k] = __float2bfloat16(f[k]);
        ll[k] = __float2bfloat16(f[k] - __bfloat162float(hh[k]));
    }
    *(uint2*)(hi + 4 * i) = *(uint2*)hh;
    *(uint2*)(lo + 4 * i) = *(uint2*)ll;
}

// Hh fp32 [b, k(1024), n(1024)]  ->  HhT split bf16 [b, n, k]
__global__ void transconv_kernel(const float* __restrict__ X,
                                 __nv_bfloat16* __restrict__ Th,
                                 __nv_bfloat16* __restrict__ Tl)
{
    __shared__ float t[32][33];
    const int b = blockIdx.z;
    const int k0 = blockIdx.x * 32, n0 = blockIdx.y * 32;
    const int tx = threadIdx.x, ty = threadIdx.y;   // 32 x 8
    const float* src = X + (long long)b * NVV * DD;
    for (int i = ty; i < 32; i += 8)
        t[i][tx] = src[(long long)(k0 + i) * DD + n0 + tx];
    __syncthreads();
    __nv_bfloat16* dh = Th + (long long)b * NVV * DD;
    __nv_bfloat16* dl = Tl + (long long)b * NVV * DD;
    for (int i = ty; i < 32; i += 8) {
        float v = t[tx][i];
        __nv_bfloat16 h = __float2bfloat16(v);
        long long o = (long long)(n0 + i) * DD + k0 + tx;
        dh[o] = h;
        dl[o] = __float2bfloat16(v - __bfloat162float(h));
    }
}

// ============================ mma.sync GEMM =================================
// C[M,N] = sum_k (Ah+Al)[m,k] * (Bh+Bl)[n,k]  (dropping Al*Bl)
// CTA tile 128x128, BK=32, 2-stage cp.async pipeline, 2 CTAs/SM.
// 8 warps as 2(M) x 4(N); warp tile 64x32.
#define BM    128
#define BN    128
#define BKC   32
#define PADK  40                        // row stride in bf16 elems (80 B)
#define ROWB  (PADK * 2)                // 80 bytes
#define ARR   (BM * ROWB)               // 10240 B per operand array
#define STAGE (4 * ARR)                 // Ah | Al | Bh | Bl = 40960 B
#define SMEM_GEMM (2 * STAGE)           // 81920 B -> 2 CTAs/SM

__global__ __launch_bounds__(256, 2)
void gemm_split(const __nv_bfloat16* __restrict__ Ahi, const __nv_bfloat16* __restrict__ Alo,
                const __nv_bfloat16* __restrict__ Bhi, const __nv_bfloat16* __restrict__ Blo,
                const float* __restrict__ bias, const int* __restrict__ mask,
                float* __restrict__ Cf,
                __nv_bfloat16* __restrict__ Chi, __nv_bfloat16* __restrict__ Clo,
                int K, int ldc,
                long long sA, long long sB, long long sC)
{
    extern __shared__ char smem[];
    const uint32_t sb = smem_u32(smem);
    const int tid = threadIdx.x;
    const int bz = blockIdx.z;
    Ahi += (long long)bz * sA;  Alo += (long long)bz * sA;
    Bhi += (long long)bz * sB;  Blo += (long long)bz * sB;
    const long long coff = (long long)bz * sC;
    const int m0 = blockIdx.y * BM;
    const int n0 = blockIdx.x * BN;

    const int lane = tid & 31, wid = tid >> 5;
    const int wm0 = (wid >> 2) * 64;      // 0 / 64
    const int wn0 = (wid & 3) * 32;       // 0 / 32 / 64 / 96

    float acc[4][4][4];
#pragma unroll
    for (int i = 0; i < 4; i++)
#pragma unroll
        for (int j = 0; j < 4; j++)
#pragma unroll
            for (int k = 0; k < 4; k++) acc[i][j][k] = 0.f;

    // ldmatrix lane address components
    const int a_row = lane & 15;
    const int a_k   = (lane >> 4) << 3;                 // 0 / 8
    const int b_row = (lane & 7) + ((lane >> 1) & 8);
    const int b_k   = ((lane >> 3) & 1) << 3;

    const int nIter = K >> 5;             // BK=32

    // ---------------- stage loader (cp.async) ----------------
    // 32 bf16 per row = 64B = 4 x 16B chunks; 128 rows per operand.
    auto load_stage = [&](int it, int s) {
        const long long k0 = (long long)it * BKC;
        const uint32_t st = sb + s * STAGE;
#pragma unroll
        for (int j = 0; j < 2; j++) {
            int idx = tid + j * 256;            // 0..511
            int r = idx >> 2, c = idx & 3;
            uint32_t so = r * ROWB + c * 16;
            long long ga = (long long)(m0 + r) * K + k0 + c * 8;
            long long gb = (long long)(n0 + r) * K + k0 + c * 8;
            CP16(st + 0 * ARR + so, (const char*)(Ahi + ga));
            CP16(st + 1 * ARR + so, (const char*)(Alo + ga));
            CP16(st + 2 * ARR + so, (const char*)(Bhi + gb));
            CP16(st + 3 * ARR + so, (const char*)(Blo + gb));
        }
        asm volatile("cp.async.commit_group;" ::: "memory");
    };

    load_stage(0, 0);

    for (int it = 0; it < nIter; ++it) {
        asm volatile("cp.async.wait_group 0;" ::: "memory");
        __syncthreads();
        if (it + 1 < nIter) load_stage(it + 1, (it + 1) & 1);

        const uint32_t st = sb + (it & 1) * STAGE;
#pragma unroll
        for (int kk = 0; kk < BKC; kk += 16) {
            uint32_t ah[4][4], al[4][4], bh[2][4], bl[2][4];
#pragma unroll
            for (int mt = 0; mt < 4; mt++) {
                uint32_t ad = st + (wm0 + 16 * mt + a_row) * ROWB + (kk + a_k) * 2;
                LDSM4(ah[mt], ad);
                LDSM4(al[mt], ad + ARR);
            }
#pragma unroll
            for (int gq = 0; gq < 2; gq++) {
                uint32_t bd = st + 2 * ARR
                            + (wn0 + gq * 16 + b_row) * ROWB + (kk + b_k) * 2;
                LDSM4(bh[gq], bd);
                LDSM4(bl[gq], bd + ARR);
            }
            // term 1: Ah * Bh
#pragma unroll
            for (int mt = 0; mt < 4; mt++)
#pragma unroll
                for (int nt = 0; nt < 4; nt++)
                    MMA(acc[mt][nt], ah[mt], bh[nt >> 1][(nt & 1) * 2],
                        bh[nt >> 1][(nt & 1) * 2 + 1]);
            // term 2: Ah * Bl
#pragma unroll
            for (int mt = 0; mt < 4; mt++)
#pragma unroll
                for (int nt = 0; nt < 4; nt++)
                    MMA(acc[mt][nt], ah[mt], bl[nt >> 1][(nt & 1) * 2],
                        bl[nt >> 1][(nt & 1) * 2 + 1]);
            // term 3: Al * Bh
#pragma unroll
            for (int mt = 0; mt < 4; mt++)
#pragma unroll
                for (int nt = 0; nt < 4; nt++)
                    MMA(acc[mt][nt], al[mt], bh[nt >> 1][(nt & 1) * 2],
                        bh[nt >> 1][(nt & 1) * 2 + 1]);
        }
        __syncthreads();
    }

    // ---------------------------- epilogue ---------------------------------
    const int g2 = lane >> 2;
    const int t2 = (lane & 3) * 2;
#pragma unroll
    for (int mt = 0; mt < 4; mt++) {
#pragma unroll
        for (int hf = 0; hf < 2; hf++) {
            int row = m0 + wm0 + mt * 16 + g2 + hf * 8;
            bool msk = (mask != nullptr) && (mask[row] == 0);
#pragma unroll
            for (int nt = 0; nt < 4; nt++) {
                int col = n0 + wn0 + nt * 8 + t2;
                float v0 = acc[mt][nt][hf * 2 + 0];
                float v1 = acc[mt][nt][hf * 2 + 1];
                if (bias) { v0 += __ldg(bias + col); v1 += __ldg(bias + col + 1); }
                if (msk)  { v0 = NEGV; v1 = NEGV; }
                long long o = coff + (long long)row * ldc + col;
                if (Cf) {
                    float2 w; w.x = v0; w.y = v1;
                    *(float2*)(Cf + o) = w;
                } else {
                    __nv_bfloat16 h0 = __float2bfloat16(v0);
                    __nv_bfloat16 h1 = __float2bfloat16(v1);
                    __nv_bfloat16 l0 = __float2bfloat16(v0 - __bfloat162float(h0));
                    __nv_bfloat16 l1 = __float2bfloat16(v1 - __bfloat162float(h1));
                    __nv_bfloat162 hh; hh.x = h0; hh.y = h1;
                    __nv_bfloat162 ll; ll.x = l0; ll.y = l1;
                    *(__nv_bfloat162*)(Chi + o) = hh;
                    *(__nv_bfloat162*)(Clo + o) = ll;
                }
            }
        }
    }
}

// ===================== softmax (writes split-bf16 P) ========================
__global__ __launch_bounds__(256)
void softmax_split_kernel(const float* __restrict__ att,
                          __nv_bfloat16* __restrict__ Ph,
                          __nv_bfloat16* __restrict__ Pl)
{
    __shared__ float red[256];
    __shared__ float ev[NVV];
    const int row = blockIdx.x;
    const float* a = att + (long long)row * NVV;
    const int tid = threadIdx.x;

    float mx = -INFINITY;
    for (int c = tid; c < NVV; c += 256) mx = fmaxf(mx, a[c]);
    red[tid] = mx; __syncthreads();
    for (int s = 128; s > 0; s >>= 1) {
        if (tid < s) red[tid] = fmaxf(red[tid], red[tid + s]);
        __syncthreads();
    }
    mx = red[0]; __syncthreads();

    float sum = 0.f;
    for (int c = tid; c < NVV; c += 256) {
        float e = __expf(a[c] - mx);
        ev[c] = e;
        sum += e;
    }
    red[tid] = sum; __syncthreads();
    for (int s = 128; s > 0; s >>= 1) {
        if (tid < s) red[tid] += red[tid + s];
        __syncthreads();
    }
    float inv = 1.f / red[0];
    for (int c = tid; c < NVV; c += 256) {
        float v = ev[c] * inv;
        __nv_bfloat16 h = __float2bfloat16(v);
        long long o = (long long)row * NVV + c;
        Ph[o] = h;
        Pl[o] = __float2bfloat16(v - __bfloat162float(h));
    }
}

// ============ fused: s = sigmoid(Vp+Hv+Zp) -> z_new[:, :D]; u = s.Wu ========
__global__ __launch_bounds__(256)
void su_kernel(const float* __restrict__ Vp, const float* __restrict__ Hv,
               const float* __restrict__ Zp, const float* __restrict__ Wu,
               float* __restrict__ zout, float* __restrict__ u)
{
    __shared__ float red[256];
    const int row = blockIdx.x;
    const int tid = threadIdx.x;
    const long long base = (long long)row * DD + tid * 4;
    float4 a = *(const float4*)(Vp + base);
    float4 b = *(const float4*)(Hv + base);
    float4 c = *(const float4*)(Zp + base);
    float4 w = *(const float4*)(Wu + tid * 4);
    float4 s;
    s.x = 1.f / (1.f + __expf(-(a.x + b.x + c.x)));
    s.y = 1.f / (1.f + __expf(-(a.y + b.y + c.y)));
    s.z = 1.f / (1.f + __expf(-(a.z + b.z + c.z)));
    s.w = 1.f / (1.f + __expf(-(a.w + b.w + c.w)));
    *(float4*)(zout + (long long)row * 2048 + tid * 4) = s;
    float acc = s.x * w.x + s.y * w.y + s.z * w.z + s.w * w.w;
    red[tid] = acc; __syncthreads();
    for (int st = 128; st > 0; st >>= 1) {
        if (tid < st) red[tid] += red[tid + st];
        __syncthreads();
    }
    if (tid == 0) u[row] = red[0];
}

__global__ __launch_bounds__(256)
void p_kernel(const float* __restrict__ u, const int* __restrict__ v_mask,
              float* __restrict__ p)
{
    __shared__ float red[256];
    __shared__ float vals[NVV];
    const int b = blockIdx.x;
    const int tid = threadIdx.x;

    float mx = -INFINITY;
    for (int j = tid; j < NVV; j += 256) {
        float val = (v_mask[b * NVV + j] == 0) ? NEGV : u[b * NVV + j];
        vals[j] = val;
        mx = fmaxf(mx, val);
    }
    red[tid] = mx; __syncthreads();
    for (int s = 128; s > 0; s >>= 1) {
        if (tid < s) red[tid] = fmaxf(red[tid], red[tid + s]);
        __syncthreads();
    }
    mx = red[0]; __syncthreads();

    float sum = 0.f;
    for (int j = tid; j < NVV; j += 256) {
        float e = __expf(vals[j] - mx);
        vals[j] = e;
        sum += e;
    }
    red[tid] = sum; __syncthreads();
    for (int s = 128; s > 0; s >>= 1) {
        if (tid < s) red[tid] += red[tid + s];
        __syncthreads();
    }
    float inv = 1.f / red[0];
    for (int j = tid; j < NVV; j += 256) p[b * NVV + j] = vals[j] * inv;
}

__global__ __launch_bounds__(256)
void g_kernel(const float* __restrict__ p, const float* __restrict__ v,
              float* __restrict__ g)
{
    __shared__ float ps[NVV];
    const int b = blockIdx.y;
    const int tid = threadIdx.x;
    for (int j = tid; j < NVV; j += 256) ps[j] = p[b * NVV + j];
    __syncthreads();
    const int d = blockIdx.x * 256 + tid;
    const float* vb = v + (long long)b * NVV * DD;
    float acc = 0.f;
#pragma unroll 4
    for (int j = 0; j < NVV; j++)
        acc = fmaf(ps[j], vb[(long long)j * DD + d], acc);
    g[b * DD + d] = acc;
}

__global__ __launch_bounds__(256)
void bcast_kernel(const float* __restrict__ g, float* __restrict__ hnew,
                  float* __restrict__ zout)
{
    long long i = (long long)blockIdx.x * 256 + threadIdx.x;
    int d = (int)(i & 1023);
    long long bi = i >> 10;
    int b = (int)(bi >> 10);
    float val = g[b * DD + d];
    hnew[i] = val;
    zout[bi * 2048 + DD + d] = val;
}

// ================================ launch ====================================
extern "C" void kernel_launch(void* const* d_in, const int* in_sizes, int n_in,
                              void* d_out, int out_size)
{
    const float* v      = (const float*)d_in[0];
    const float* h      = (const float*)d_in[1];
    const float* z      = (const float*)d_in[2];
    const int*   v_mask = (const int*)  d_in[3];
    const int*   h_mask = (const int*)  d_in[4];
    const float* Wv_w   = (const float*)d_in[5];
    const float* Wv_b   = (const float*)d_in[6];
    const float* Wh_w   = (const float*)d_in[7];
    const float* qv_w   = (const float*)d_in[8];
    const float* qv_b   = (const float*)d_in[9];
    const float* kh_w   = (const float*)d_in[10];
    const float* Wz_w   = (const float*)d_in[11];
    const float* Wu_w   = (const float*)d_in[12];

    float* out  = (float*)d_out;
    float* hnew = out;
    float* zout = out + (long long)MROWS * DD;

    cudaFuncSetAttribute(gemm_split, cudaFuncAttributeMaxDynamicSharedMemorySize,
                         SMEM_GEMM);

#define SYM(p, s) do { void* _t; cudaGetSymbolAddress(&_t, s); p = (decltype(p))_t; } while (0)
    __nv_bfloat16 *vhi, *vlo, *hhi, *hlo, *zhi, *zlo;
    __nv_bfloat16 *Wvh, *Wvl, *qvh, *qvl, *Whh, *Whl, *khh, *khl, *Wzh, *Wzl;
    __nv_bfloat16 *Qh, *Ql, *Kh, *Kl, *Ph, *Pl, *HTh, *HTl;
    float *Vp, *Hh, *Zp, *Att, *Hv, *U, *P, *G;
    SYM(vhi, g_vhi); SYM(vlo, g_vlo); SYM(hhi, g_hhi); SYM(hlo, g_hlo);
    SYM(zhi, g_zhi); SYM(zlo, g_zlo);
    SYM(Wvh, g_Wvh); SYM(Wvl, g_Wvl); SYM(qvh, g_qvh); SYM(qvl, g_qvl);
    SYM(Whh, g_Whh); SYM(Whl, g_Whl); SYM(khh, g_khh); SYM(khl, g_khl);
    SYM(Wzh, g_Wzh); SYM(Wzl, g_Wzl);
    SYM(Qh, g_Qh); SYM(Ql, g_Ql); SYM(Kh, g_Kh); SYM(Kl, g_Kl);
    SYM(Ph, g_Ph); SYM(Pl, g_Pl); SYM(HTh, g_HTh); SYM(HTl, g_HTl);
    SYM(Vp, g_Vp); SYM(Hh, g_Hh); SYM(Zp, g_Zp); SYM(Att, g_att); SYM(Hv, g_Hv);
    SYM(U, g_u); SYM(P, g_p); SYM(G, g_g);
#undef SYM

    // ---- fp32 -> split bf16 conversions ----
    auto conv = [&](const float* x, __nv_bfloat16* hi, __nv_bfloat16* lo, long long n) {
        long long n4 = n >> 2;
        conv_split<<<(unsigned)((n4 + 255) / 256), 256>>>(x, hi, lo, n4);
    };
    conv(v, vhi, vlo, (long long)MROWS * DD);
    conv(h, hhi, hlo, (long long)MROWS * DD);
    conv(z, zhi, zlo, (long long)MROWS * 2 * DD);
    conv(Wv_w, Wvh, Wvl, (long long)DD * DD);
    conv(qv_w, qvh, qvl, (long long)DD * DD);
    conv(Wh_w, Whh, Whl, (long long)DD * DD);
    conv(kh_w, khh, khl, (long long)DD * DD);
    conv(Wz_w, Wzh, Wzl, (long long)DD * 2 * DD);

    const long long PB = (long long)NVV * NVV;
    dim3 gBig(DD / BN, MROWS / BM, 1);     // (8,128,1)
    dim3 gBat(DD / BN, NVV / BM, BB);      // (8,8,16)

    // ---- projections ----
    gemm_split<<<gBig, 256, SMEM_GEMM>>>(vhi, vlo, Wvh, Wvl, Wv_b, nullptr,
                                         Vp, nullptr, nullptr, DD, DD, 0, 0, 0);
    gemm_split<<<gBig, 256, SMEM_GEMM>>>(vhi, vlo, qvh, qvl, qv_b, nullptr,
                                         nullptr, Qh, Ql, DD, DD, 0, 0, 0);
    gemm_split<<<gBig, 256, SMEM_GEMM>>>(hhi, hlo, Whh, Whl, nullptr, nullptr,
                                         Hh, nullptr, nullptr, DD, DD, 0, 0, 0);
    gemm_split<<<gBig, 256, SMEM_GEMM>>>(hhi, hlo, khh, khl, nullptr, h_mask,
                                         nullptr, Kh, Kl, DD, DD, 0, 0, 0);
    gemm_split<<<gBig, 256, SMEM_GEMM>>>(zhi, zlo, Wzh, Wzl, nullptr, nullptr,
                                         Zp, nullptr, nullptr, 2 * DD, DD, 0, 0, 0);

    // ---- attention ----
    gemm_split<<<gBat, 256, SMEM_GEMM>>>(Qh, Ql, Kh, Kl, nullptr, nullptr,
                                         Att, nullptr, nullptr, DD, NVV, PB, PB, PB);
    softmax_split_kernel<<<MROWS, 256>>>(Att, Ph, Pl);
    transconv_kernel<<<dim3(32, 32, BB), dim3(32, 8)>>>(Hh, HTh, HTl);
    gemm_split<<<gBat, 256, SMEM_GEMM>>>(Ph, Pl, HTh, HTl, nullptr, nullptr,
                                         Hv, nullptr, nullptr, NVV, DD, PB, PB, PB);

    // ---- tail ----
    su_kernel<<<MROWS, 256>>>(Vp, Hv, Zp, Wu_w, zout, U);
    p_kernel<<<BB, 256>>>(U, v_mask, P);
    g_kernel<<<dim3(DD / 256, BB), 256>>>(P, v, G);
    bcast_kernel<<<(MROWS * DD) / 256, 256>>>(G, hnew, zout);
}

// round 8
// speedup vs baseline: 1.4911x; 1.4911x over previous
#include <cuda_runtime.h>
#include <cuda_bf16.h>
#include <cstdint>
#include <math.h>

// ---------------------------------------------------------------------------
// stack_latent_attention (B=16, NV=NH=D=1024)
// GEMMs via mma.sync.m16n8k16 bf16, split-bf16 3-term (hh + hl + lh).
// R8: R5-proven 128x128 tile / 64x32 warp tile / BK=64, now 3-stage
//     cp.async pipeline (depth-2 prefetch); fused s+u tail; launch order
//     arranged so ncu (-s 5 -c 1) captures a gemm_split.
// ---------------------------------------------------------------------------

#define BB    16
#define NVV   1024
#define DD    1024
#define MROWS (BB * NVV)
#define NEGV  (-1e30f)

// ============================ PTX helpers ===================================
__device__ __forceinline__ uint32_t smem_u32(const void* p) {
    uint32_t a;
    asm("{ .reg .u64 t; cvta.to.shared.u64 t, %1; cvt.u32.u64 %0, t; }"
        : "=r"(a) : "l"(p));
    return a;
}

#define CP16(s, g) \
    asm volatile("cp.async.cg.shared.global [%0], [%1], 16;" \
                 :: "r"(s), "l"(g) : "memory")

#define LDSM4(r, addr) \
    asm volatile("ldmatrix.sync.aligned.m8n8.x4.shared.b16 {%0,%1,%2,%3}, [%4];" \
                 : "=r"((r)[0]), "=r"((r)[1]), "=r"((r)[2]), "=r"((r)[3]) \
                 : "r"(addr))

#define MMA(c, a, b0, b1) \
    asm volatile("mma.sync.aligned.m16n8k16.row.col.f32.bf16.bf16.f32 " \
                 "{%0,%1,%2,%3}, {%4,%5,%6,%7}, {%8,%9}, {%0,%1,%2,%3};" \
                 : "+f"((c)[0]), "+f"((c)[1]), "+f"((c)[2]), "+f"((c)[3]) \
                 : "r"((a)[0]), "r"((a)[1]), "r"((a)[2]), "r"((a)[3]), \
                   "r"(b0), "r"(b1))

// ============================ scratch =======================================
__device__ __align__(256) __nv_bfloat16 g_vhi[MROWS * DD], g_vlo[MROWS * DD];
__device__ __align__(256) __nv_bfloat16 g_hhi[MROWS * DD], g_hlo[MROWS * DD];
__device__ __align__(256) __nv_bfloat16 g_zhi[MROWS * 2 * DD], g_zlo[MROWS * 2 * DD];
__device__ __align__(256) __nv_bfloat16 g_Wvh[DD * DD], g_Wvl[DD * DD];
__device__ __align__(256) __nv_bfloat16 g_qvh[DD * DD], g_qvl[DD * DD];
__device__ __align__(256) __nv_bfloat16 g_Whh[DD * DD], g_Whl[DD * DD];
__device__ __align__(256) __nv_bfloat16 g_khh[DD * DD], g_khl[DD * DD];
__device__ __align__(256) __nv_bfloat16 g_Wzh[DD * 2 * DD], g_Wzl[DD * 2 * DD];
__device__ __align__(256) __nv_bfloat16 g_Qh[MROWS * DD],  g_Ql[MROWS * DD];
__device__ __align__(256) __nv_bfloat16 g_Kh[MROWS * DD],  g_Kl[MROWS * DD];
__device__ __align__(256) __nv_bfloat16 g_Ph[MROWS * DD],  g_Pl[MROWS * DD];
__device__ __align__(256) __nv_bfloat16 g_HTh[MROWS * DD], g_HTl[MROWS * DD];
__device__ __align__(256) float g_Vp[MROWS * DD];
__device__ __align__(256) float g_Hh[MROWS * DD];
__device__ __align__(256) float g_Zp[MROWS * DD];
__device__ __align__(256) float g_att[(long long)BB * NVV * NVV];
__device__ __align__(256) float g_Hv[MROWS * DD];
__device__ float g_u[MROWS];
__device__ float g_p[MROWS];
__device__ float g_g[BB * DD];

// ======================== conversion kernels ================================
__global__ __launch_bounds__(256)
void conv_split(const float* __restrict__ x, __nv_bfloat16* __restrict__ hi,
                __nv_bfloat16* __restrict__ lo, long long n4)
{
    long long i = (long long)blockIdx.x * 256 + threadIdx.x;
    if (i >= n4) return;
    float4 v = ((const float4*)x)[i];
    __nv_bfloat16 hh[4], ll[4];
    float f[4] = {v.x, v.y, v.z, v.w};
#pragma unroll
    for (int k = 0; k < 4; k++) {
        hh[k] = __float2bfloat16(f[k]);
        ll[k] = __float2bfloat16(f[k] - __bfloat162float(hh[k]));
    }
    *(uint2*)(hi + 4 * i) = *(uint2*)hh;
    *(uint2*)(lo + 4 * i) = *(uint2*)ll;
}

// Hh fp32 [b, k(1024), n(1024)]  ->  HhT split bf16 [b, n, k]
__global__ void transconv_kernel(const float* __restrict__ X,
                                 __nv_bfloat16* __restrict__ Th,
                                 __nv_bfloat16* __restrict__ Tl)
{
    __shared__ float t[32][33];
    const int b = blockIdx.z;
    const int k0 = blockIdx.x * 32, n0 = blockIdx.y * 32;
    const int tx = threadIdx.x, ty = threadIdx.y;   // 32 x 8
    const float* src = X + (long long)b * NVV * DD;
    for (int i = ty; i < 32; i += 8)
        t[i][tx] = src[(long long)(k0 + i) * DD + n0 + tx];
    __syncthreads();
    __nv_bfloat16* dh = Th + (long long)b * NVV * DD;
    __nv_bfloat16* dl = Tl + (long long)b * NVV * DD;
    for (int i = ty; i < 32; i += 8) {
        float v = t[tx][i];
        __nv_bfloat16 h = __float2bfloat16(v);
        long long o = (long long)(n0 + i) * DD + k0 + tx;
        dh[o] = h;
        dl[o] = __float2bfloat16(v - __bfloat162float(h));
    }
}

// ============================ mma.sync GEMM =================================
// C[M,N] = sum_k (Ah+Al)[m,k] * (Bh+Bl)[n,k]  (dropping Al*Bl)
// CTA tile 128x128, BK=64, 3-stage cp.async pipeline (depth-2 prefetch).
// 8 warps as 2(M) x 4(N); warp tile 64x32.
#define BM    128
#define BN    128
#define BKC   64
#define PADK  72                        // row stride in bf16 elems (144 B)
#define ROWB  (PADK * 2)                // 144 bytes
#define ARR   (BM * ROWB)               // 18432 B per operand array
#define STAGE (4 * ARR)                 // Ah | Al | Bh | Bl = 73728 B
#define NSTG  3
#define SMEM_GEMM (NSTG * STAGE)        // 221184 B

__global__ __launch_bounds__(256)
void gemm_split(const __nv_bfloat16* __restrict__ Ahi, const __nv_bfloat16* __restrict__ Alo,
                const __nv_bfloat16* __restrict__ Bhi, const __nv_bfloat16* __restrict__ Blo,
                const float* __restrict__ bias, const int* __restrict__ mask,
                float* __restrict__ Cf,
                __nv_bfloat16* __restrict__ Chi, __nv_bfloat16* __restrict__ Clo,
                int K, int ldc,
                long long sA, long long sB, long long sC)
{
    extern __shared__ char smem[];
    const uint32_t sb = smem_u32(smem);
    const int tid = threadIdx.x;
    const int bz = blockIdx.z;
    Ahi += (long long)bz * sA;  Alo += (long long)bz * sA;
    Bhi += (long long)bz * sB;  Blo += (long long)bz * sB;
    const long long coff = (long long)bz * sC;
    const int m0 = blockIdx.y * BM;
    const int n0 = blockIdx.x * BN;

    const int lane = tid & 31, wid = tid >> 5;
    const int wm0 = (wid >> 2) * 64;      // 0 / 64
    const int wn0 = (wid & 3) * 32;       // 0 / 32 / 64 / 96

    float acc[4][4][4];
#pragma unroll
    for (int i = 0; i < 4; i++)
#pragma unroll
        for (int j = 0; j < 4; j++)
#pragma unroll
            for (int k = 0; k < 4; k++) acc[i][j][k] = 0.f;

    // ldmatrix lane address components
    const int a_row = lane & 15;
    const int a_k   = (lane >> 4) << 3;                 // 0 / 8
    const int b_row = (lane & 7) + ((lane >> 1) & 8);
    const int b_k   = ((lane >> 3) & 1) << 3;

    const int nIter = K >> 6;             // BK=64

    // ---------------- stage loader (cp.async) ----------------
    // 64 bf16 per row = 128B = 8 x 16B chunks; 128 rows per operand.
    auto load_stage = [&](int it, int s) {
        const long long k0 = (long long)it * BKC;
        const uint32_t st = sb + s * STAGE;
#pragma unroll
        for (int j = 0; j < 4; j++) {
            int idx = tid + j * 256;            // 0..1023
            int r = idx >> 3, c = idx & 7;
            uint32_t so = r * ROWB + c * 16;
            long long ga = (long long)(m0 + r) * K + k0 + c * 8;
            long long gb = (long long)(n0 + r) * K + k0 + c * 8;
            CP16(st + 0 * ARR + so, (const char*)(Ahi + ga));
            CP16(st + 1 * ARR + so, (const char*)(Alo + ga));
            CP16(st + 2 * ARR + so, (const char*)(Bhi + gb));
            CP16(st + 3 * ARR + so, (const char*)(Blo + gb));
        }
        asm volatile("cp.async.commit_group;" ::: "memory");
    };

    load_stage(0, 0);
    if (nIter > 1) load_stage(1, 1);

    int slot = 0;
    for (int it = 0; it < nIter; ++it) {
        asm volatile("cp.async.wait_group 1;" ::: "memory");
        __syncthreads();
        // slot (it+2)%3 is free: all warps passed the barrier, so all reads of
        // stage it-1 (which lived there) are complete.
        if (it + 2 < nIter) {
            int ns = slot + 2; if (ns >= NSTG) ns -= NSTG;
            load_stage(it + 2, ns);
        } else {
            asm volatile("cp.async.commit_group;" ::: "memory"); // keep count
        }

        const uint32_t st = sb + slot * STAGE;
#pragma unroll
        for (int kk = 0; kk < BKC; kk += 16) {
            uint32_t ah[4][4], al[4][4], bh[2][4], bl[2][4];
#pragma unroll
            for (int mt = 0; mt < 4; mt++) {
                uint32_t ad = st + (wm0 + 16 * mt + a_row) * ROWB + (kk + a_k) * 2;
                LDSM4(ah[mt], ad);
                LDSM4(al[mt], ad + ARR);
            }
#pragma unroll
            for (int gq = 0; gq < 2; gq++) {
                uint32_t bd = st + 2 * ARR
                            + (wn0 + gq * 16 + b_row) * ROWB + (kk + b_k) * 2;
                LDSM4(bh[gq], bd);
                LDSM4(bl[gq], bd + ARR);
            }
            // term 1: Ah * Bh
#pragma unroll
            for (int mt = 0; mt < 4; mt++)
#pragma unroll
                for (int nt = 0; nt < 4; nt++)
                    MMA(acc[mt][nt], ah[mt], bh[nt >> 1][(nt & 1) * 2],
                        bh[nt >> 1][(nt & 1) * 2 + 1]);
            // term 2: Ah * Bl
#pragma unroll
            for (int mt = 0; mt < 4; mt++)
#pragma unroll
                for (int nt = 0; nt < 4; nt++)
                    MMA(acc[mt][nt], ah[mt], bl[nt >> 1][(nt & 1) * 2],
                        bl[nt >> 1][(nt & 1) * 2 + 1]);
            // term 3: Al * Bh
#pragma unroll
            for (int mt = 0; mt < 4; mt++)
#pragma unroll
                for (int nt = 0; nt < 4; nt++)
                    MMA(acc[mt][nt], al[mt], bh[nt >> 1][(nt & 1) * 2],
                        bh[nt >> 1][(nt & 1) * 2 + 1]);
        }
        if (++slot == NSTG) slot = 0;
    }

    // ---------------------------- epilogue ---------------------------------
    const int g2 = lane >> 2;
    const int t2 = (lane & 3) * 2;
#pragma unroll
    for (int mt = 0; mt < 4; mt++) {
#pragma unroll
        for (int hf = 0; hf < 2; hf++) {
            int row = m0 + wm0 + mt * 16 + g2 + hf * 8;
            bool msk = (mask != nullptr) && (mask[row] == 0);
#pragma unroll
            for (int nt = 0; nt < 4; nt++) {
                int col = n0 + wn0 + nt * 8 + t2;
                float v0 = acc[mt][nt][hf * 2 + 0];
                float v1 = acc[mt][nt][hf * 2 + 1];
                if (bias) { v0 += __ldg(bias + col); v1 += __ldg(bias + col + 1); }
                if (msk)  { v0 = NEGV; v1 = NEGV; }
                long long o = coff + (long long)row * ldc + col;
                if (Cf) {
                    float2 w; w.x = v0; w.y = v1;
                    *(float2*)(Cf + o) = w;
                } else {
                    __nv_bfloat16 h0 = __float2bfloat16(v0);
                    __nv_bfloat16 h1 = __float2bfloat16(v1);
                    __nv_bfloat16 l0 = __float2bfloat16(v0 - __bfloat162float(h0));
                    __nv_bfloat16 l1 = __float2bfloat16(v1 - __bfloat162float(h1));
                    __nv_bfloat162 hh; hh.x = h0; hh.y = h1;
                    __nv_bfloat162 ll; ll.x = l0; ll.y = l1;
                    *(__nv_bfloat162*)(Chi + o) = hh;
                    *(__nv_bfloat162*)(Clo + o) = ll;
                }
            }
        }
    }
}

// ===================== softmax (writes split-bf16 P) ========================
__global__ __launch_bounds__(256)
void softmax_split_kernel(const float* __restrict__ att,
                          __nv_bfloat16* __restrict__ Ph,
                          __nv_bfloat16* __restrict__ Pl)
{
    __shared__ float red[256];
    __shared__ float ev[NVV];
    const int row = blockIdx.x;
    const float* a = att + (long long)row * NVV;
    const int tid = threadIdx.x;

    float mx = -INFINITY;
    for (int c = tid; c < NVV; c += 256) mx = fmaxf(mx, a[c]);
    red[tid] = mx; __syncthreads();
    for (int s = 128; s > 0; s >>= 1) {
        if (tid < s) red[tid] = fmaxf(red[tid], red[tid + s]);
        __syncthreads();
    }
    mx = red[0]; __syncthreads();

    float sum = 0.f;
    for (int c = tid; c < NVV; c += 256) {
        float e = __expf(a[c] - mx);
        ev[c] = e;
        sum += e;
    }
    red[tid] = sum; __syncthreads();
    for (int s = 128; s > 0; s >>= 1) {
        if (tid < s) red[tid] += red[tid + s];
        __syncthreads();
    }
    float inv = 1.f / red[0];
    for (int c = tid; c < NVV; c += 256) {
        float v = ev[c] * inv;
        __nv_bfloat16 h = __float2bfloat16(v);
        long long o = (long long)row * NVV + c;
        Ph[o] = h;
        Pl[o] = __float2bfloat16(v - __bfloat162float(h));
    }
}

// ============ fused: s = sigmoid(Vp+Hv+Zp) -> z_new[:, :D]; u = s.Wu ========
__global__ __launch_bounds__(256)
void su_kernel(const float* __restrict__ Vp, const float* __restrict__ Hv,
               const float* __restrict__ Zp, const float* __restrict__ Wu,
               float* __restrict__ zout, float* __restrict__ u)
{
    __shared__ float red[256];
    const int row = blockIdx.x;
    const int tid = threadIdx.x;
    const long long base = (long long)row * DD + tid * 4;
    float4 a = *(const float4*)(Vp + base);
    float4 b = *(const float4*)(Hv + base);
    float4 c = *(const float4*)(Zp + base);
    float4 w = *(const float4*)(Wu + tid * 4);
    float4 s;
    s.x = 1.f / (1.f + __expf(-(a.x + b.x + c.x)));
    s.y = 1.f / (1.f + __expf(-(a.y + b.y + c.y)));
    s.z = 1.f / (1.f + __expf(-(a.z + b.z + c.z)));
    s.w = 1.f / (1.f + __expf(-(a.w + b.w + c.w)));
    *(float4*)(zout + (long long)row * 2048 + tid * 4) = s;
    float acc = s.x * w.x + s.y * w.y + s.z * w.z + s.w * w.w;
    red[tid] = acc; __syncthreads();
    for (int st = 128; st > 0; st >>= 1) {
        if (tid < st) red[tid] += red[tid + st];
        __syncthreads();
    }
    if (tid == 0) u[row] = red[0];
}

__global__ __launch_bounds__(256)
void p_kernel(const float* __restrict__ u, const int* __restrict__ v_mask,
              float* __restrict__ p)
{
    __shared__ float red[256];
    __shared__ float vals[NVV];
    const int b = blockIdx.x;
    const int tid = threadIdx.x;

    float mx = -INFINITY;
    for (int j = tid; j < NVV; j += 256) {
        float val = (v_mask[b * NVV + j] == 0) ? NEGV : u[b * NVV + j];
        vals[j] = val;
        mx = fmaxf(mx, val);
    }
    red[tid] = mx; __syncthreads();
    for (int s = 128; s > 0; s >>= 1) {
        if (tid < s) red[tid] = fmaxf(red[tid], red[tid + s]);
        __syncthreads();
    }
    mx = red[0]; __syncthreads();

    float sum = 0.f;
    for (int j = tid; j < NVV; j += 256) {
        float e = __expf(vals[j] - mx);
        vals[j] = e;
        sum += e;
    }
    red[tid] = sum; __syncthreads();
    for (int s = 128; s > 0; s >>= 1) {
        if (tid < s) red[tid] += red[tid + s];
        __syncthreads();
    }
    float inv = 1.f / red[0];
    for (int j = tid; j < NVV; j += 256) p[b * NVV + j] = vals[j] * inv;
}

__global__ __launch_bounds__(256)
void g_kernel(const float* __restrict__ p, const float* __restrict__ v,
              float* __restrict__ g)
{
    __shared__ float ps[NVV];
    const int b = blockIdx.y;
    const int tid = threadIdx.x;
    for (int j = tid; j < NVV; j += 256) ps[j] = p[b * NVV + j];
    __syncthreads();
    const int d = blockIdx.x * 256 + tid;
    const float* vb = v + (long long)b * NVV * DD;
    float acc = 0.f;
#pragma unroll 4
    for (int j = 0; j < NVV; j++)
        acc = fmaf(ps[j], vb[(long long)j * DD + d], acc);
    g[b * DD + d] = acc;
}

__global__ __launch_bounds__(256)
void bcast_kernel(const float* __restrict__ g, float* __restrict__ hnew,
                  float* __restrict__ zout)
{
    long long i = (long long)blockIdx.x * 256 + threadIdx.x;
    int d = (int)(i & 1023);
    long long bi = i >> 10;
    int b = (int)(bi >> 10);
    float val = g[b * DD + d];
    hnew[i] = val;
    zout[bi * 2048 + DD + d] = val;
}

// ================================ launch ====================================
extern "C" void kernel_launch(void* const* d_in, const int* in_sizes, int n_in,
                              void* d_out, int out_size)
{
    const float* v      = (const float*)d_in[0];
    const float* h      = (const float*)d_in[1];
    const float* z      = (const float*)d_in[2];
    const int*   v_mask = (const int*)  d_in[3];
    const int*   h_mask = (const int*)  d_in[4];
    const float* Wv_w   = (const float*)d_in[5];
    const float* Wv_b   = (const float*)d_in[6];
    const float* Wh_w   = (const float*)d_in[7];
    const float* qv_w   = (const float*)d_in[8];
    const float* qv_b   = (const float*)d_in[9];
    const float* kh_w   = (const float*)d_in[10];
    const float* Wz_w   = (const float*)d_in[11];
    const float* Wu_w   = (const float*)d_in[12];

    float* out  = (float*)d_out;
    float* hnew = out;
    float* zout = out + (long long)MROWS * DD;

    cudaFuncSetAttribute(gemm_split, cudaFuncAttributeMaxDynamicSharedMemorySize,
                         SMEM_GEMM);

#define SYM(p, s) do { void* _t; cudaGetSymbolAddress(&_t, s); p = (decltype(p))_t; } while (0)
    __nv_bfloat16 *vhi, *vlo, *hhi, *hlo, *zhi, *zlo;
    __nv_bfloat16 *Wvh, *Wvl, *qvh, *qvl, *Whh, *Whl, *khh, *khl, *Wzh, *Wzl;
    __nv_bfloat16 *Qh, *Ql, *Kh, *Kl, *Ph, *Pl, *HTh, *HTl;
    float *Vp, *Hh, *Zp, *Att, *Hv, *U, *P, *G;
    SYM(vhi, g_vhi); SYM(vlo, g_vlo); SYM(hhi, g_hhi); SYM(hlo, g_hlo);
    SYM(zhi, g_zhi); SYM(zlo, g_zlo);
    SYM(Wvh, g_Wvh); SYM(Wvl, g_Wvl); SYM(qvh, g_qvh); SYM(qvl, g_qvl);
    SYM(Whh, g_Whh); SYM(Whl, g_Whl); SYM(khh, g_khh); SYM(khl, g_khl);
    SYM(Wzh, g_Wzh); SYM(Wzl, g_Wzl);
    SYM(Qh, g_Qh); SYM(Ql, g_Ql); SYM(Kh, g_Kh); SYM(Kl, g_Kl);
    SYM(Ph, g_Ph); SYM(Pl, g_Pl); SYM(HTh, g_HTh); SYM(HTl, g_HTl);
    SYM(Vp, g_Vp); SYM(Hh, g_Hh); SYM(Zp, g_Zp); SYM(Att, g_att); SYM(Hv, g_Hv);
    SYM(U, g_u); SYM(P, g_p); SYM(G, g_g);
#undef SYM

    auto conv = [&](const float* x, __nv_bfloat16* hi, __nv_bfloat16* lo, long long n) {
        long long n4 = n >> 2;
        conv_split<<<(unsigned)((n4 + 255) / 256), 256>>>(x, hi, lo, n4);
    };

    const long long PB = (long long)NVV * NVV;
    dim3 gBig(DD / BN, MROWS / BM, 1);     // (8,128,1)
    dim3 gBat(DD / BN, NVV / BM, BB);      // (8,8,16)

    // Launch order arranged so launch #6 (ncu -s 5 -c 1) is a gemm_split.
    conv(z, zhi, zlo, (long long)MROWS * 2 * DD);          // 1
    conv(Wz_w, Wzh, Wzl, (long long)DD * 2 * DD);          // 2
    conv(v, vhi, vlo, (long long)MROWS * DD);              // 3
    conv(Wv_w, Wvh, Wvl, (long long)DD * DD);              // 4
    conv(qv_w, qvh, qvl, (long long)DD * DD);              // 5
    gemm_split<<<gBig, 256, SMEM_GEMM>>>(zhi, zlo, Wzh, Wzl, nullptr, nullptr,
                                         Zp, nullptr, nullptr, 2 * DD, DD, 0, 0, 0); // 6 <- profiled
    conv(h, hhi, hlo, (long long)MROWS * DD);
    conv(Wh_w, Whh, Whl, (long long)DD * DD);
    conv(kh_w, khh, khl, (long long)DD * DD);

    // ---- remaining projections ----
    gemm_split<<<gBig, 256, SMEM_GEMM>>>(vhi, vlo, Wvh, Wvl, Wv_b, nullptr,
                                         Vp, nullptr, nullptr, DD, DD, 0, 0, 0);
    gemm_split<<<gBig, 256, SMEM_GEMM>>>(vhi, vlo, qvh, qvl, qv_b, nullptr,
                                         nullptr, Qh, Ql, DD, DD, 0, 0, 0);
    gemm_split<<<gBig, 256, SMEM_GEMM>>>(hhi, hlo, Whh, Whl, nullptr, nullptr,
                                         Hh, nullptr, nullptr, DD, DD, 0, 0, 0);
    gemm_split<<<gBig, 256, SMEM_GEMM>>>(hhi, hlo, khh, khl, nullptr, h_mask,
                                         nullptr, Kh, Kl, DD, DD, 0, 0, 0);

    // ---- attention ----
    gemm_split<<<gBat, 256, SMEM_GEMM>>>(Qh, Ql, Kh, Kl, nullptr, nullptr,
                                         Att, nullptr, nullptr, DD, NVV, PB, PB, PB);
    softmax_split_kernel<<<MROWS, 256>>>(Att, Ph, Pl);
    transconv_kernel<<<dim3(32, 32, BB), dim3(32, 8)>>>(Hh, HTh, HTl);
    gemm_split<<<gBat, 256, SMEM_GEMM>>>(Ph, Pl, HTh, HTl, nullptr, nullptr,
                                         Hv, nullptr, nullptr, NVV, DD, PB, PB, PB);

    // ---- tail ----
    su_kernel<<<MROWS, 256>>>(Vp, Hv, Zp, Wu_w, zout, U);
    p_kernel<<<BB, 256>>>(U, v_mask, P);
    g_kernel<<<dim3(DD / 256, BB), 256>>>(P, v, G);
    bcast_kernel<<<(MROWS * DD) / 256, 256>>>(G, hnew, zout);
}